// round 2
// baseline (speedup 1.0000x reference)
#include <cuda_runtime.h>
#include <math.h>

#define NN 100000
#define EE 1600000
#define FIN 512
#define HH 128
#define KKEEP 50000
#define NCH 98  // ceil(NN/1024)

typedef unsigned long long ull;

// ------------------------- device scratch (globals) -------------------------
__device__ __align__(16) float g_y [(size_t)NN * HH];   // scaled xw buffer (y = ds * X@W)
__device__ __align__(16) float g_x1[(size_t)NN * HH];
__device__ __align__(16) float g_x2[(size_t)NN * HH];
__device__ __align__(16) float g_x3[(size_t)NN * HH];
__device__ float g_ds[NN];
__device__ int   g_degcnt[NN];
__device__ int   g_rowptr[NN + 1];
__device__ int   g_fill[NN];
__device__ int   g_csr[EE];
__device__ int   g_chunksum[NCH];
__device__ int   g_chunkoff[NCH];
__device__ float g_ysc[NN];       // scaled score lin
__device__ float g_score[NN];
__device__ unsigned g_ukey[NN];
__device__ unsigned g_hist[256];
__device__ unsigned g_prefix;
__device__ unsigned g_kprime;
__device__ int   g_nties;
__device__ int   g_tieidx[NN];
__device__ int   g_tieflag[NN];
__device__ float g_gmax[384];
__device__ float g_gsum[384];

// ------------------------- small helpers -------------------------
__device__ __forceinline__ void ffma2(ull &d, ull a, ull b) {
    asm("fma.rn.f32x2 %0, %1, %2, %0;" : "+l"(d) : "l"(a), "l"(b));
}
__device__ __forceinline__ ull pack2(float lo, float hi) {
    ull r;
    asm("mov.b64 %0, {%1, %2};" : "=l"(r) : "r"(__float_as_uint(lo)), "r"(__float_as_uint(hi)));
    return r;
}
__device__ __forceinline__ void unpack2(ull p, float &lo, float &hi) {
    unsigned a, b;
    asm("mov.b64 {%0, %1}, %2;" : "=r"(a), "=r"(b) : "l"(p));
    lo = __uint_as_float(a); hi = __uint_as_float(b);
}
__device__ __forceinline__ unsigned fkey(float f) {
    unsigned u = __float_as_uint(f);
    return (u & 0x80000000u) ? ~u : (u | 0x80000000u);  // monotone: bigger float -> bigger key
}
__device__ __forceinline__ void atomicMaxF(float *addr, float val) {
    if (val >= 0.f) atomicMax((int *)addr, __float_as_int(val));
    else            atomicMin((unsigned *)addr, __float_as_uint(val));
}
__device__ __forceinline__ const float *pickX(int w) {
    return w == 1 ? g_x1 : (w == 2 ? g_x2 : g_x3);
}

// ------------------------- init -------------------------
__global__ void k_init() {
    int i = blockIdx.x * blockDim.x + threadIdx.x;
    if (i < NN) { g_degcnt[i] = 0; g_fill[i] = 0; g_tieflag[i] = 0; }
    if (i < 384) { g_gmax[i] = -3.402823466e38f; g_gsum[i] = 0.f; }
    if (i < 256) g_hist[i] = 0u;
    if (i == 0) { g_prefix = 0u; g_kprime = (unsigned)KKEEP; g_nties = 0; }
}

// ------------------------- degree / CSR build (edge_index is int32!) -------------------------
__global__ void k_count(const int *__restrict__ ei) {
    int e = blockIdx.x * blockDim.x + threadIdx.x;
    if (e >= EE) return;
    int d = ei[EE + e];
    atomicAdd(&g_degcnt[d], 1);
}
__global__ void k_node() {
    int i = blockIdx.x * blockDim.x + threadIdx.x;
    if (i >= NN) return;
    g_ds[i] = rsqrtf((float)(g_degcnt[i] + 1));
}
__global__ void k_chunksum() {
    __shared__ int sm[256];
    int t = threadIdx.x, b = blockIdx.x;
    int s = 0;
    for (int j = t; j < 1024; j += 256) {
        int idx = b * 1024 + j;
        if (idx < NN) s += g_degcnt[idx];
    }
    sm[t] = s; __syncthreads();
    for (int o = 128; o; o >>= 1) { if (t < o) sm[t] += sm[t + o]; __syncthreads(); }
    if (t == 0) g_chunksum[b] = sm[0];
}
__global__ void k_scanchunks() {
    int run = 0;
    for (int c = 0; c < NCH; ++c) { g_chunkoff[c] = run; run += g_chunksum[c]; }
    g_rowptr[NN] = EE;
}
__global__ void k_scanwrite() {
    __shared__ int sd[1024];
    int t = threadIdx.x, b = blockIdx.x;
    int idx = b * 1024 + t;
    int v = (idx < NN) ? g_degcnt[idx] : 0;
    int x = v;
    for (int o = 1; o < 1024; o <<= 1) {
        sd[t] = x; __syncthreads();
        if (t >= o) x += sd[t - o];
        __syncthreads();
    }
    if (idx < NN) g_rowptr[idx] = g_chunkoff[b] + x - v;
}
__global__ void k_scatter(const int *__restrict__ ei) {
    int e = blockIdx.x * blockDim.x + threadIdx.x;
    if (e >= EE) return;
    int s = ei[e];
    int d = ei[EE + e];
    int pos = g_rowptr[d] + atomicAdd(&g_fill[d], 1);
    g_csr[pos] = s;
}

// ------------------------- GEMM: Y = ds[i] * (A @ W), W is [Kin,128] -------------------------
// BM=64 BN=128 BK=32, 256 threads, each thread 4 rows x 8 cols via fma.rn.f32x2
__global__ __launch_bounds__(256) void k_gemm(const float *__restrict__ Aext, int useExt,
                                              int whichSrc,
                                              const float *__restrict__ W, int Kin) {
    __shared__ float As[32][68];   // transposed A tile, padded (68*4B row = 16B aligned)
    __shared__ float Bs[32][128];
    const float *A = useExt ? Aext : pickX(whichSrc);
    int tid = threadIdx.x;
    int tx = tid & 15;   // col group
    int ty = tid >> 4;   // row group
    int row0 = blockIdx.x * 64;
    ull acc[4][4];
#pragma unroll
    for (int r = 0; r < 4; ++r)
#pragma unroll
        for (int c = 0; c < 4; ++c) acc[r][c] = 0ull;

    for (int k0 = 0; k0 < Kin; k0 += 32) {
#pragma unroll
        for (int it = 0; it < 2; ++it) {
            int s = tid + it * 256;
            int m = s >> 3, kq = s & 7;
            int row = row0 + m;
            float4 v = make_float4(0.f, 0.f, 0.f, 0.f);
            if (row < NN) v = *(const float4 *)&A[(size_t)row * Kin + k0 + kq * 4];
            As[kq * 4 + 0][m] = v.x; As[kq * 4 + 1][m] = v.y;
            As[kq * 4 + 2][m] = v.z; As[kq * 4 + 3][m] = v.w;
        }
#pragma unroll
        for (int it = 0; it < 4; ++it) {
            int s = tid + it * 256;
            int kk = s >> 5, jq = s & 31;
            *(float4 *)&Bs[kk][jq * 4] = *(const float4 *)&W[(size_t)(k0 + kk) * 128 + jq * 4];
        }
        __syncthreads();
#pragma unroll
        for (int kk = 0; kk < 32; ++kk) {
            float4 a4 = *(const float4 *)&As[kk][ty * 4];
            ull ap0 = pack2(a4.x, a4.x), ap1 = pack2(a4.y, a4.y);
            ull ap2 = pack2(a4.z, a4.z), ap3 = pack2(a4.w, a4.w);
            const ull *bp = (const ull *)&Bs[kk][tx * 8];
            ull b0 = bp[0], b1 = bp[1], b2 = bp[2], b3 = bp[3];
            ffma2(acc[0][0], ap0, b0); ffma2(acc[0][1], ap0, b1); ffma2(acc[0][2], ap0, b2); ffma2(acc[0][3], ap0, b3);
            ffma2(acc[1][0], ap1, b0); ffma2(acc[1][1], ap1, b1); ffma2(acc[1][2], ap1, b2); ffma2(acc[1][3], ap1, b3);
            ffma2(acc[2][0], ap2, b0); ffma2(acc[2][1], ap2, b1); ffma2(acc[2][2], ap2, b2); ffma2(acc[2][3], ap2, b3);
            ffma2(acc[3][0], ap3, b0); ffma2(acc[3][1], ap3, b1); ffma2(acc[3][2], ap3, b2); ffma2(acc[3][3], ap3, b3);
        }
        __syncthreads();
    }
#pragma unroll
    for (int r = 0; r < 4; ++r) {
        int row = row0 + ty * 4 + r;
        if (row >= NN) continue;
        float sc = g_ds[row];
        float o[8];
#pragma unroll
        for (int c = 0; c < 4; ++c) unpack2(acc[r][c], o[2 * c], o[2 * c + 1]);
        float4 v0 = make_float4(o[0] * sc, o[1] * sc, o[2] * sc, o[3] * sc);
        float4 v1 = make_float4(o[4] * sc, o[5] * sc, o[6] * sc, o[7] * sc);
        *(float4 *)&g_y[(size_t)row * 128 + tx * 8]     = v0;
        *(float4 *)&g_y[(size_t)row * 128 + tx * 8 + 4] = v1;
    }
}

// ------------------------- aggregation: out = relu(ds[d]*(sum_nb y + y[d]) + b) -------------------------
__global__ __launch_bounds__(256) void k_agg(const float *__restrict__ bias, int whichDst) {
    int gw = (blockIdx.x * 256 + threadIdx.x) >> 5;
    int lane = threadIdx.x & 31;
    if (gw >= NN) return;
    float *out = (float *)pickX(whichDst);
    int start = g_rowptr[gw], end = g_rowptr[gw + 1];
    int col = lane * 4;
    float4 acc = *(const float4 *)&g_y[(size_t)gw * 128 + col];  // self term
    for (int e = start; e < end; ++e) {
        int s = g_csr[e];
        float4 v = *(const float4 *)&g_y[(size_t)s * 128 + col];
        acc.x += v.x; acc.y += v.y; acc.z += v.z; acc.w += v.w;
    }
    float sc = g_ds[gw];
    float4 b4 = *(const float4 *)&bias[col];
    float4 o;
    o.x = fmaxf(fmaf(acc.x, sc, b4.x), 0.f);
    o.y = fmaxf(fmaf(acc.y, sc, b4.y), 0.f);
    o.z = fmaxf(fmaf(acc.z, sc, b4.z), 0.f);
    o.w = fmaxf(fmaf(acc.w, sc, b4.w), 0.f);
    *(float4 *)&out[(size_t)gw * 128 + col] = o;
}

// ------------------------- score: ys = ds * (cat . Ws), then GCN-aggregate scalar -------------------------
__global__ __launch_bounds__(256) void k_score_lin(const float *__restrict__ Ws) {
    __shared__ float sW[384];
    int tid = threadIdx.x;
    for (int i = tid; i < 384; i += 256) sW[i] = Ws[i];
    __syncthreads();
    int gw = (blockIdx.x * 256 + tid) >> 5;
    int lane = tid & 31;
    if (gw >= NN) return;
    size_t base = (size_t)gw * 128;
    float s = 0.f;
#pragma unroll
    for (int t = 0; t < 4; ++t) {
        int c = lane + 32 * t;
        s += g_x1[base + c] * sW[c] + g_x2[base + c] * sW[128 + c] + g_x3[base + c] * sW[256 + c];
    }
    for (int o = 16; o; o >>= 1) s += __shfl_down_sync(0xFFFFFFFFu, s, o);
    if (lane == 0) g_ysc[gw] = g_ds[gw] * s;
}
__global__ __launch_bounds__(256) void k_score_agg(const float *__restrict__ bs) {
    int gw = (blockIdx.x * 256 + threadIdx.x) >> 5;
    int lane = threadIdx.x & 31;
    if (gw >= NN) return;
    int start = g_rowptr[gw], end = g_rowptr[gw + 1];
    float s = 0.f;
    for (int e = start + lane; e < end; e += 32) s += g_ysc[g_csr[e]];
    for (int o = 16; o; o >>= 1) s += __shfl_down_sync(0xFFFFFFFFu, s, o);
    if (lane == 0) {
        float tot = s + g_ysc[gw];
        float sc = fmaf(g_ds[gw], tot, bs[0]);
        g_score[gw] = sc;
        g_ukey[gw] = fkey(sc);
    }
}

// ------------------------- radix select (4 passes of 8 bits) -------------------------
__global__ void k_hist(int pass) {
    __shared__ unsigned sh[256];
    int t = threadIdx.x;
    sh[t] = 0u; __syncthreads();
    int i = blockIdx.x * 256 + t;
    if (i < NN) {
        unsigned u = g_ukey[i];
        bool m = (pass == 0) || ((u >> (32 - 8 * pass)) == g_prefix);
        if (m) atomicAdd(&sh[(u >> (24 - 8 * pass)) & 255u], 1u);
    }
    __syncthreads();
    if (sh[t]) atomicAdd(&g_hist[t], sh[t]);
}
__global__ void k_select() {
    __shared__ unsigned h[256];
    int t = threadIdx.x;
    h[t] = g_hist[t];
    g_hist[t] = 0u;  // ready for next pass
    __syncthreads();
    if (t == 0) {
        unsigned kp = g_kprime, c = 0;
        int b;
        for (b = 255; b >= 0; --b) {
            if (c + h[b] >= kp) break;
            c += h[b];
        }
        if (b < 0) b = 0;  // defensive
        g_prefix = (g_prefix << 8) | (unsigned)b;
        g_kprime = kp - c;
    }
}
__global__ void k_ties() {
    int i = blockIdx.x * blockDim.x + threadIdx.x;
    if (i >= NN) return;
    if (g_ukey[i] == g_prefix) {
        int p = atomicAdd(&g_nties, 1);
        g_tieidx[p] = i;
    }
}
__global__ void k_tieresolve() {
    int M = g_nties;
    unsigned R = g_kprime;
    for (int j = threadIdx.x; j < M; j += blockDim.x) {
        int idx = g_tieidx[j];
        unsigned rank = 0;
        for (int l = 0; l < M; ++l) rank += (g_tieidx[l] < idx) ? 1u : 0u;
        if (rank < R) g_tieflag[idx] = 1;  // lower index wins (jax top_k tie-break)
    }
}

// ------------------------- pooling (max + sum over kept nodes, 384 dims) -------------------------
__global__ __launch_bounds__(384) void k_pool() {
    int c = threadIdx.x;  // 0..383
    const float *xa = (c < 128) ? g_x1 : ((c < 256) ? g_x2 : g_x3);
    int cc = c & 127;
    unsigned T = g_prefix;
    float mx = -3.402823466e38f, sm = 0.f;
    for (int i = blockIdx.x; i < NN; i += gridDim.x) {
        unsigned u = g_ukey[i];
        if (u < T) continue;
        if (u == T && !g_tieflag[i]) continue;
        float g = tanhf(g_score[i]);
        float v = xa[(size_t)i * 128 + cc] * g;
        mx = fmaxf(mx, v);
        sm += v;
    }
    atomicMaxF(&g_gmax[c], mx);
    atomicAdd(&g_gsum[c], sm);
}

// ------------------------- final MLP head (single block) -------------------------
__global__ __launch_bounds__(128) void k_mlp(const float *__restrict__ Wl1, const float *__restrict__ bl1,
                                             const float *__restrict__ Wl2, const float *__restrict__ bl2,
                                             const float *__restrict__ Wl3, const float *__restrict__ bl3,
                                             float *__restrict__ out) {
    __shared__ float h[768], h1[128], h2[64], lg[10];
    int t = threadIdx.x;
    for (int c = t; c < 384; c += 128) {
        h[c] = g_gmax[c];
        h[384 + c] = g_gsum[c] * (1.0f / KKEEP);
    }
    __syncthreads();
    float s = bl1[t];
    for (int i = 0; i < 768; ++i) s = fmaf(h[i], Wl1[i * 128 + t], s);
    h1[t] = fmaxf(s, 0.f);
    __syncthreads();
    if (t < 64) {
        float s2 = bl2[t];
        for (int i = 0; i < 128; ++i) s2 = fmaf(h1[i], Wl2[i * 64 + t], s2);
        h2[t] = fmaxf(s2, 0.f);
    }
    __syncthreads();
    if (t < 10) {
        float s3 = bl3[t];
        for (int i = 0; i < 64; ++i) s3 = fmaf(h2[i], Wl3[i * 10 + t], s3);
        lg[t] = s3;
    }
    __syncthreads();
    if (t == 0) {
        float m = lg[0];
        for (int j = 1; j < 10; ++j) m = fmaxf(m, lg[j]);
        float se = 0.f;
        for (int j = 0; j < 10; ++j) se += expf(lg[j] - m);
        float lse = m + logf(se);
        for (int j = 0; j < 10; ++j) out[j] = lg[j] - lse;
    }
}

// ------------------------- launch -------------------------
extern "C" void kernel_launch(void *const *d_in, const int *in_sizes, int n_in,
                              void *d_out, int out_size) {
    const float *x      = (const float *)d_in[0];
    const int   *ei     = (const int *)d_in[1];   // int32 (jax x64 disabled)
    // d_in[2] = batch (unused, single graph)
    const float *W1 = (const float *)d_in[3],  *b1  = (const float *)d_in[4];
    const float *W2 = (const float *)d_in[5],  *b2  = (const float *)d_in[6];
    const float *W3 = (const float *)d_in[7],  *b3  = (const float *)d_in[8];
    const float *Ws = (const float *)d_in[9],  *bs  = (const float *)d_in[10];
    const float *Wl1 = (const float *)d_in[11], *bl1 = (const float *)d_in[12];
    const float *Wl2 = (const float *)d_in[13], *bl2 = (const float *)d_in[14];
    const float *Wl3 = (const float *)d_in[15], *bl3 = (const float *)d_in[16];
    float *out = (float *)d_out;

    const int nblkN = (NN + 255) / 256;
    const int nblkE = (EE + 255) / 256;
    const int nblkW = (NN * 32 + 255) / 256;   // 1 warp per node
    const int nblkG = (NN + 63) / 64;

    k_init<<<nblkN, 256>>>();
    // CSR build
    k_count<<<nblkE, 256>>>(ei);
    k_node<<<nblkN, 256>>>();
    k_chunksum<<<NCH, 256>>>();
    k_scanchunks<<<1, 1>>>();
    k_scanwrite<<<NCH, 1024>>>();
    k_scatter<<<nblkE, 256>>>(ei);
    // GCN layer 1
    k_gemm<<<nblkG, 256>>>(x, 1, 0, W1, FIN);
    k_agg<<<nblkW, 256>>>(b1, 1);
    // GCN layer 2
    k_gemm<<<nblkG, 256>>>(nullptr, 0, 1, W2, HH);
    k_agg<<<nblkW, 256>>>(b2, 2);
    // GCN layer 3
    k_gemm<<<nblkG, 256>>>(nullptr, 0, 2, W3, HH);
    k_agg<<<nblkW, 256>>>(b3, 3);
    // score GCN (1 channel)
    k_score_lin<<<nblkW, 256>>>(Ws);
    k_score_agg<<<nblkW, 256>>>(bs);
    // exact top-k threshold via 4x8-bit radix select
    for (int p = 0; p < 4; ++p) {
        k_hist<<<nblkN, 256>>>(p);
        k_select<<<1, 256>>>();
    }
    k_ties<<<nblkN, 256>>>();
    k_tieresolve<<<1, 256>>>();
    // gated max/mean readout over kept nodes
    k_pool<<<512, 384>>>();
    // MLP head + log_softmax
    k_mlp<<<1, 128>>>(Wl1, bl1, Wl2, bl2, Wl3, bl3, out);
}